// round 6
// baseline (speedup 1.0000x reference)
#include <cuda_runtime.h>
#include <cstdint>

// Problem constants (fixed shapes)
#define N_NODES 50000
#define T_STEPS 12
#define F_IN    128
#define HEADS   4
#define FILT    32
#define DDIM    128          // HEADS*FILT
#define E_EDGES 800000
#define NEG_SLOPE 0.2f
#define D3      (3 * DDIM)   // 384

#define ND (N_NODES * DDIM)
#define NH (N_NODES * HEADS)

// ---------------- scratch (device globals; no allocation in kernel_launch) ----------------
__device__ float d_h_feat[ND];
__device__ float d_alS[NH];
__device__ float d_alD[NH];
__device__ float d_denom[NH];
__device__ float d_acc[ND];
__device__ float d_ghbuf[N_NODES * D3];
__device__ float d_hstate[ND];     // exact fp32 GRU state
__device__ float d_h32[ND];        // tf32-rounded copy (GEMM input)
__device__ float d_WihT[DDIM * D3];
__device__ float d_WhhT[DDIM * D3];

__device__ __forceinline__ float tf32r(float x) {
    uint32_t u;
    asm("cvt.rna.tf32.f32 %0, %1;" : "=r"(u) : "f"(x));
    return __uint_as_float(u);
}

__device__ __forceinline__ void mma16n8k8(float* c, const uint32_t* a, const uint32_t* b) {
    asm volatile(
        "mma.sync.aligned.m16n8k8.row.col.f32.tf32.tf32.f32 "
        "{%0,%1,%2,%3}, {%4,%5,%6,%7}, {%8,%9}, {%0,%1,%2,%3};\n"
        : "+f"(c[0]), "+f"(c[1]), "+f"(c[2]), "+f"(c[3])
        : "r"(a[0]), "r"(a[1]), "r"(a[2]), "r"(a[3]), "r"(b[0]), "r"(b[1]));
}

__device__ __forceinline__ void cp_async16(uint32_t saddr, const void* gptr, int srcsize) {
    asm volatile("cp.async.cg.shared.global [%0], [%1], 16, %2;"
                 :: "r"(saddr), "l"(gptr), "r"(srcsize));
}

// ---------------- small utility kernels ----------------
__global__ void zero_kernel(float* p, float* q, int n) {
    int i = blockIdx.x * blockDim.x + threadIdx.x;
    if (i < n) { p[i] = 0.0f; q[i] = 0.0f; }
}

// WT[k*D3 + j] = tf32(W[j*DDIM + k])   (W is [3D, D] row-major)
__global__ void transpose_w(const float* __restrict__ W, float* __restrict__ WT) {
    int idx = blockIdx.x * blockDim.x + threadIdx.x;
    if (idx < D3 * DDIM) {
        int j = idx / DDIM;
        int k = idx - j * DDIM;
        WT[k * D3 + j] = tf32r(W[idx]);
    }
}

// ---------------- GAT GEMM + fused attention-logit epilogue ----------------
__global__ __launch_bounds__(256, 2) void gemm_att(
    const float* __restrict__ A, int lda, int M,
    const float* __restrict__ W,
    float* __restrict__ C,
    const float* __restrict__ a_src, const float* __restrict__ a_dst,
    float* __restrict__ alS, float* __restrict__ alD,
    float* __restrict__ denom, float* __restrict__ acc)
{
    __shared__ float As[128][36];   // [m][k]
    __shared__ float Ws[32][132];   // [k][n]
    __shared__ float sS[128 * HEADS];
    __shared__ float sD[128 * HEADS];

    const int tid  = threadIdx.x;
    const int lane = tid & 31;
    const int wid  = tid >> 5;
    const int wm   = (wid & 3) * 32;
    const int wn   = (wid >> 2) * 64;
    const int row0 = blockIdx.x * 128;

    float cacc[2][8][4];
#pragma unroll
    for (int mf = 0; mf < 2; mf++)
#pragma unroll
        for (int nf = 0; nf < 8; nf++)
#pragma unroll
            for (int q = 0; q < 4; q++) cacc[mf][nf][q] = 0.0f;

    const int lq = lane >> 2;
    const int lr = lane & 3;

    if (tid < 128 * HEADS / 2) { sS[tid] = 0.f; sS[tid + 256] = 0.f;
                                 sD[tid] = 0.f; sD[tid + 256] = 0.f; }

    for (int k0 = 0; k0 < 128; k0 += 32) {
        __syncthreads();
#pragma unroll
        for (int i = 0; i < 4; i++) {
            int f = tid + i * 256;
            int r = f >> 3, kq = f & 7;
            int gr = row0 + r;
            float4 v = make_float4(0.f, 0.f, 0.f, 0.f);
            if (gr < M) v = *(const float4*)&A[(long)gr * lda + k0 + kq * 4];
            float4 cv = make_float4(tf32r(v.x), tf32r(v.y), tf32r(v.z), tf32r(v.w));
            *(float4*)&As[r][kq * 4] = cv;
        }
#pragma unroll
        for (int i = 0; i < 4; i++) {
            int f = tid + i * 256;
            int kk = f >> 5, c4 = f & 31;
            float4 v = *(const float4*)&W[(long)(k0 + kk) * DDIM + c4 * 4];
            float4 cv = make_float4(tf32r(v.x), tf32r(v.y), tf32r(v.z), tf32r(v.w));
            *(float4*)&Ws[kk][c4 * 4] = cv;
        }
        __syncthreads();

#pragma unroll
        for (int s = 0; s < 4; s++) {
            const int ks = s * 8;
            uint32_t af[2][4];
#pragma unroll
            for (int mf = 0; mf < 2; mf++) {
                int r = wm + mf * 16 + lq;
                int kc = ks + lr;
                af[mf][0] = __float_as_uint(As[r][kc]);
                af[mf][1] = __float_as_uint(As[r + 8][kc]);
                af[mf][2] = __float_as_uint(As[r][kc + 4]);
                af[mf][3] = __float_as_uint(As[r + 8][kc + 4]);
            }
            uint32_t bf[8][2];
#pragma unroll
            for (int nf = 0; nf < 8; nf++) {
                int cc = wn + nf * 8 + lq;
                int kr = ks + lr;
                bf[nf][0] = __float_as_uint(Ws[kr][cc]);
                bf[nf][1] = __float_as_uint(Ws[kr + 4][cc]);
            }
#pragma unroll
            for (int mf = 0; mf < 2; mf++)
#pragma unroll
                for (int nf = 0; nf < 8; nf++)
                    mma16n8k8(cacc[mf][nf], af[mf], bf[nf]);
        }
    }

    // ===== fused attention epilogue =====
    __syncthreads();
    {
        float aSv[8][2], aDv[8][2];
#pragma unroll
        for (int nf = 0; nf < 8; nf++) {
            int cc = wn + nf * 8 + lr * 2;
            aSv[nf][0] = a_src[cc];     aSv[nf][1] = a_src[cc + 1];
            aDv[nf][0] = a_dst[cc];     aDv[nf][1] = a_dst[cc + 1];
        }
#pragma unroll
        for (int mf = 0; mf < 2; mf++) {
#pragma unroll
            for (int half = 0; half < 2; half++) {
                int lrow = wm + mf * 16 + lq + half * 8;
                int h0 = wn >> 5;
                float pS0 = 0.f, pD0 = 0.f, pS1 = 0.f, pD1 = 0.f;
#pragma unroll
                for (int nf = 0; nf < 4; nf++) {
                    float v0 = cacc[mf][nf][half * 2], v1 = cacc[mf][nf][half * 2 + 1];
                    pS0 += v0 * aSv[nf][0] + v1 * aSv[nf][1];
                    pD0 += v0 * aDv[nf][0] + v1 * aDv[nf][1];
                }
#pragma unroll
                for (int nf = 4; nf < 8; nf++) {
                    float v0 = cacc[mf][nf][half * 2], v1 = cacc[mf][nf][half * 2 + 1];
                    pS1 += v0 * aSv[nf][0] + v1 * aSv[nf][1];
                    pD1 += v0 * aDv[nf][0] + v1 * aDv[nf][1];
                }
                atomicAdd(&sS[lrow * HEADS + h0], pS0);
                atomicAdd(&sD[lrow * HEADS + h0], pD0);
                atomicAdd(&sS[lrow * HEADS + h0 + 1], pS1);
                atomicAdd(&sD[lrow * HEADS + h0 + 1], pD1);
            }
        }
    }
    __syncthreads();
    for (int i = tid; i < 128 * HEADS; i += 256) {
        int lrow = i >> 2;
        int gr = row0 + lrow;
        if (gr < M) {
            float sg = sS[i], dg = sD[i];
            float v = sg + dg;
            float e = v > 0.0f ? v : NEG_SLOPE * v;
            float w = __expf(e);
            alS[(long)gr * HEADS + (i & 3)] = sg;
            alD[(long)gr * HEADS + (i & 3)] = dg;
            denom[(long)gr * HEADS + (i & 3)] = w;
            sD[i] = w;
        }
    }
    __syncthreads();
#pragma unroll
    for (int mf = 0; mf < 2; mf++) {
        int lrow = wm + mf * 16 + lq;
#pragma unroll
        for (int nf = 0; nf < 8; nf++) {
            int cc = wn + nf * 8 + lr * 2;
            int head = cc >> 5;
            int r_b = row0 + lrow;
            if (r_b < M) {
                float w = sD[lrow * HEADS + head];
                float2 o = make_float2(cacc[mf][nf][0], cacc[mf][nf][1]);
                *(float2*)&C[(long)r_b * DDIM + cc] = o;
                *(float2*)&acc[(long)r_b * DDIM + cc] = make_float2(o.x * w, o.y * w);
            }
            if (r_b + 8 < M) {
                float w = sD[(lrow + 8) * HEADS + head];
                float2 o = make_float2(cacc[mf][nf][2], cacc[mf][nf][3]);
                *(float2*)&C[(long)(r_b + 8) * DDIM + cc] = o;
                *(float2*)&acc[(long)(r_b + 8) * DDIM + cc] = make_float2(o.x * w, o.y * w);
            }
        }
    }
}

// ---------------- pipelined GEMM (used for gh): A[M,128] @ W[128,NO] + bias ----------------
#define AS_STAGE (128 * 36)
#define WS_STAGE (32 * 132)
#define PIPE_SMEM_BYTES ((2 * AS_STAGE + 2 * WS_STAGE) * 4)

__global__ __launch_bounds__(256, 2) void gemm_tf32_pipe(
    const float* __restrict__ A, int M,
    const float* __restrict__ W, int NO,
    const float* __restrict__ bias,
    float* __restrict__ C)
{
    extern __shared__ float sm[];
    float* AsBase = sm;
    float* WsBase = sm + 2 * AS_STAGE;

    const int tid  = threadIdx.x;
    const int lane = tid & 31;
    const int wid  = tid >> 5;
    const int wm   = (wid & 3) * 32;
    const int wn   = (wid >> 2) * 64;
    const int row0 = blockIdx.x * 128;
    const int c0   = blockIdx.y * 128;
    const int lq   = lane >> 2;
    const int lr   = lane & 3;

    float cacc[2][8][4];
#pragma unroll
    for (int mf = 0; mf < 2; mf++)
#pragma unroll
        for (int nf = 0; nf < 8; nf++)
#pragma unroll
            for (int q = 0; q < 4; q++) cacc[mf][nf][q] = 0.0f;

    const uint32_t sA = (uint32_t)__cvta_generic_to_shared(AsBase);
    const uint32_t sW = (uint32_t)__cvta_generic_to_shared(WsBase);

    const int ar = tid >> 3;
    const int akq = tid & 7;
    const int wkk = tid >> 5;
    const int wc4 = tid & 31;

#define PREFETCH(it_)                                                              \
    {                                                                              \
        int k0_ = (it_) * 32;                                                      \
        int st_ = (it_) & 1;                                                       \
        _Pragma("unroll")                                                          \
        for (int i = 0; i < 4; i++) {                                              \
            int r_ = ar + i * 32;                                                  \
            int gr_ = row0 + r_;                                                   \
            uint32_t sa_ = sA + (uint32_t)((st_ * AS_STAGE + r_ * 36 + akq * 4) * 4); \
            const float* gp_ = &A[(long)(gr_ < M ? gr_ : 0) * 128 + k0_ + akq * 4]; \
            cp_async16(sa_, gp_, gr_ < M ? 16 : 0);                                \
        }                                                                          \
        _Pragma("unroll")                                                          \
        for (int i = 0; i < 4; i++) {                                              \
            int kk_ = wkk + i * 8;                                                 \
            uint32_t sa_ = sW + (uint32_t)((st_ * WS_STAGE + kk_ * 132 + wc4 * 4) * 4); \
            const float* gp_ = &W[(long)(k0_ + kk_) * NO + c0 + wc4 * 4];           \
            cp_async16(sa_, gp_, 16);                                              \
        }                                                                          \
        asm volatile("cp.async.commit_group;");                                    \
    }

    PREFETCH(0);
#pragma unroll
    for (int it = 0; it < 4; it++) {
        if (it < 3) {
            PREFETCH(it + 1);
            asm volatile("cp.async.wait_group 1;");
        } else {
            asm volatile("cp.async.wait_group 0;");
        }
        __syncthreads();
        const float* Asc = AsBase + (it & 1) * AS_STAGE;
        const float* Wsc = WsBase + (it & 1) * WS_STAGE;
#pragma unroll
        for (int s = 0; s < 4; s++) {
            const int ks = s * 8;
            uint32_t af[2][4];
#pragma unroll
            for (int mf = 0; mf < 2; mf++) {
                int r = wm + mf * 16 + lq;
                int kc = ks + lr;
                af[mf][0] = __float_as_uint(Asc[r * 36 + kc]);
                af[mf][1] = __float_as_uint(Asc[(r + 8) * 36 + kc]);
                af[mf][2] = __float_as_uint(Asc[r * 36 + kc + 4]);
                af[mf][3] = __float_as_uint(Asc[(r + 8) * 36 + kc + 4]);
            }
            uint32_t bf[8][2];
#pragma unroll
            for (int nf = 0; nf < 8; nf++) {
                int cc = wn + nf * 8 + lq;
                int kr = ks + lr;
                bf[nf][0] = __float_as_uint(Wsc[kr * 132 + cc]);
                bf[nf][1] = __float_as_uint(Wsc[(kr + 4) * 132 + cc]);
            }
#pragma unroll
            for (int mf = 0; mf < 2; mf++)
#pragma unroll
                for (int nf = 0; nf < 8; nf++)
                    mma16n8k8(cacc[mf][nf], af[mf], bf[nf]);
        }
        __syncthreads();
    }
#undef PREFETCH

#pragma unroll
    for (int mf = 0; mf < 2; mf++) {
        int r_b = row0 + wm + mf * 16 + lq;
#pragma unroll
        for (int nf = 0; nf < 8; nf++) {
            int cc = c0 + wn + nf * 8 + lr * 2;
            float b0 = bias[cc];
            float b1 = bias[cc + 1];
            if (r_b < M)
                *(float2*)&C[(long)r_b * NO + cc] =
                    make_float2(cacc[mf][nf][0] + b0, cacc[mf][nf][1] + b1);
            if (r_b + 8 < M)
                *(float2*)&C[(long)(r_b + 8) * NO + cc] =
                    make_float2(cacc[mf][nf][2] + b0, cacc[mf][nf][3] + b1);
        }
    }
}

// ---------------- fused GRU kernel ----------------
// For 64 rows: finalize g from (acc, denom, bg), GEMM g @ WihT (all 3 gate
// blocks, 384 cols) + bih, then GRU gates vs gh + hstate. Writes h, h32.
#define GFW_STAGE (3 * 32 * 132)                    // W floats per stage
#define GF_AS     (64 * 36)
#define GF_SMEM_BYTES ((2 * GFW_STAGE + GF_AS + 256) * 4)

__global__ __launch_bounds__(256, 1) void gru_fused(
    const float* __restrict__ acc, const float* __restrict__ denom,
    const float* __restrict__ bg,
    const float* __restrict__ WT,      // WihT [128][384], tf32
    const float* __restrict__ bih,
    const float* __restrict__ gh,      // [M][384]
    float* __restrict__ h, float* __restrict__ h32, int M)
{
    extern __shared__ float sm[];
    float* Wbuf = sm;                    // [2][3][32][132]
    float* As   = sm + 2 * GFW_STAGE;    // [64][36]
    float* sInv = As + GF_AS;            // [256] = 64 rows x 4 heads

    const int tid  = threadIdx.x;
    const int lane = tid & 31;
    const int wid  = tid >> 5;
    const int wm   = (wid & 1) * 32;     // row group
    const int wn   = (wid >> 1) * 32;    // col group (within a 128-wide gate)
    const int lq   = lane >> 2;
    const int lr   = lane & 3;
    const int row0 = blockIdx.x * 64;

    // per-(row,head) inverse denominators
    {
        int n = row0 + (tid >> 2);
        sInv[tid] = (n < M) ? 1.0f / (denom[(long)n * HEADS + (tid & 3)] + 1e-16f) : 0.0f;
    }

    float cacc[3][2][4][4];
#pragma unroll
    for (int ga = 0; ga < 3; ga++)
#pragma unroll
        for (int mf = 0; mf < 2; mf++)
#pragma unroll
            for (int nf = 0; nf < 4; nf++)
#pragma unroll
                for (int q = 0; q < 4; q++) cacc[ga][mf][nf][q] = 0.0f;

    const uint32_t sW = (uint32_t)__cvta_generic_to_shared(Wbuf);

    // W prefetch: 3 gates x 32 rows x 32 col-quads = 3072 slots, 12/thread
#define WPF(it_)                                                                    \
    {                                                                               \
        int k0_ = (it_) * 32;                                                       \
        int st_ = (it_) & 1;                                                        \
        _Pragma("unroll")                                                           \
        for (int j = 0; j < 12; j++) {                                              \
            int s_ = tid + j * 256;                                                 \
            int ga_ = s_ >> 10;                                                     \
            int rem_ = s_ & 1023;                                                   \
            int kk_ = rem_ >> 5, c4_ = rem_ & 31;                                   \
            uint32_t dst_ = sW + (uint32_t)((st_ * GFW_STAGE + ga_ * (32 * 132) +   \
                                             kk_ * 132 + c4_ * 4) * 4);             \
            cp_async16(dst_, &WT[(long)(k0_ + kk_) * D3 + ga_ * 128 + c4_ * 4], 16); \
        }                                                                           \
        asm volatile("cp.async.commit_group;");                                     \
    }

    // A prefetch to regs: 64 rows x 8 quads = 512 slots, 2/thread
    const int arr = tid >> 3;            // rows: arr, arr+32
    const int akq = tid & 7;
    float4 aA[2];
#pragma unroll
    for (int i = 0; i < 2; i++) {
        int r = arr + i * 32;
        int gr = row0 + r;
        aA[i] = (gr < M) ? *(const float4*)&acc[(long)gr * DDIM + akq * 4]
                         : make_float4(0.f, 0.f, 0.f, 0.f);
    }
    WPF(0);

#pragma unroll
    for (int it = 0; it < 4; it++) {
        __syncthreads();   // As free (prev compute + sInv ready on it==0)
        // finalize: g = tf32(relu(acc*inv + bg)), head == chunk index
#pragma unroll
        for (int i = 0; i < 2; i++) {
            int r = arr + i * 32;
            float inv = sInv[r * 4 + it];
            float4 b = *(const float4*)&bg[it * 32 + akq * 4];
            float4 v;
            v.x = tf32r(fmaxf(aA[i].x * inv + b.x, 0.0f));
            v.y = tf32r(fmaxf(aA[i].y * inv + b.y, 0.0f));
            v.z = tf32r(fmaxf(aA[i].z * inv + b.z, 0.0f));
            v.w = tf32r(fmaxf(aA[i].w * inv + b.w, 0.0f));
            *(float4*)&As[r * 36 + akq * 4] = v;
        }
        if (it < 3) {
            // prefetch next A chunk + next W stage
#pragma unroll
            for (int i = 0; i < 2; i++) {
                int r = arr + i * 32;
                int gr = row0 + r;
                aA[i] = (gr < M) ? *(const float4*)&acc[(long)gr * DDIM + (it + 1) * 32 + akq * 4]
                                 : make_float4(0.f, 0.f, 0.f, 0.f);
            }
            WPF(it + 1);
            asm volatile("cp.async.wait_group 1;");
        } else {
            asm volatile("cp.async.wait_group 0;");
        }
        __syncthreads();

        const float* Wc = Wbuf + (it & 1) * GFW_STAGE;
#pragma unroll
        for (int s = 0; s < 4; s++) {
            const int ks = s * 8;
            uint32_t af[2][4];
#pragma unroll
            for (int mf = 0; mf < 2; mf++) {
                int r = wm + mf * 16 + lq;
                int kc = ks + lr;
                af[mf][0] = __float_as_uint(As[r * 36 + kc]);
                af[mf][1] = __float_as_uint(As[(r + 8) * 36 + kc]);
                af[mf][2] = __float_as_uint(As[r * 36 + kc + 4]);
                af[mf][3] = __float_as_uint(As[(r + 8) * 36 + kc + 4]);
            }
#pragma unroll
            for (int ga = 0; ga < 3; ga++) {
#pragma unroll
                for (int nf = 0; nf < 4; nf++) {
                    int cc = wn + nf * 8 + lq;
                    int kr = ks + lr;
                    uint32_t bf[2];
                    bf[0] = __float_as_uint(Wc[ga * (32 * 132) + kr * 132 + cc]);
                    bf[1] = __float_as_uint(Wc[ga * (32 * 132) + (kr + 4) * 132 + cc]);
#pragma unroll
                    for (int mf = 0; mf < 2; mf++)
                        mma16n8k8(cacc[ga][mf][nf], af[mf], bf);
                }
            }
        }
    }
#undef WPF

    // ===== GRU gate epilogue =====
#pragma unroll
    for (int mf = 0; mf < 2; mf++) {
#pragma unroll
        for (int half = 0; half < 2; half++) {
            int row = row0 + wm + mf * 16 + lq + half * 8;
            if (row >= M) continue;
#pragma unroll
            for (int nf = 0; nf < 4; nf++) {
                int col = wn + nf * 8 + lr * 2;
                const float* ghr = &gh[(long)row * D3 + col];
                float2 g0 = *(const float2*)&ghr[0];
                float2 g1 = *(const float2*)&ghr[128];
                float2 g2 = *(const float2*)&ghr[256];
                float2 hv = *(const float2*)&h[(long)row * DDIM + col];
                float2 ho, h32o;
#pragma unroll
                for (int q = 0; q < 2; q++) {
                    float ir = cacc[0][mf][nf][half * 2 + q] + bih[col + q];
                    float iz = cacc[1][mf][nf][half * 2 + q] + bih[128 + col + q];
                    float in_ = cacc[2][mf][nf][half * 2 + q] + bih[256 + col + q];
                    float hr = (&g0.x)[q];
                    float hz = (&g1.x)[q];
                    float hn = (&g2.x)[q];
                    float hvf = (&hv.x)[q];
                    float r = 1.0f / (1.0f + __expf(-(ir + hr)));
                    float z = 1.0f / (1.0f + __expf(-(iz + hz)));
                    float nn = tanhf(in_ + r * hn);
                    float hnew = (1.0f - z) * nn + z * hvf;
                    (&ho.x)[q] = hnew;
                    (&h32o.x)[q] = tf32r(hnew);
                }
                *(float2*)&h[(long)row * DDIM + col] = ho;
                *(float2*)&h32[(long)row * DDIM + col] = h32o;
            }
        }
    }
}

// ---------------- edge pass ----------------
__device__ __forceinline__ void red_add_v4(float* addr, float a, float b, float c, float d) {
    asm volatile("red.global.add.v4.f32 [%0], {%1,%2,%3,%4};"
                 :: "l"(addr), "f"(a), "f"(b), "f"(c), "f"(d) : "memory");
}

__global__ __launch_bounds__(256) void edge_kernel(
    const int* __restrict__ src_arr, const int* __restrict__ dst_arr,
    const float* __restrict__ alS, const float* __restrict__ alD,
    const float* __restrict__ h,
    float* __restrict__ denom, float* __restrict__ acc)
{
    long gw = (long)blockIdx.x * (blockDim.x >> 5) + (threadIdx.x >> 5);
    if (gw >= E_EDGES) return;
    int lane = threadIdx.x & 31;
    int head = lane >> 3;

    int s = src_arr[gw];
    int d = dst_arr[gw];

    float v = alS[s * HEADS + head] + alD[d * HEADS + head];
    float e = v > 0.0f ? v : NEG_SLOPE * v;
    float w = __expf(e);

    if ((lane & 7) == 0) atomicAdd(&denom[d * HEADS + head], w);

    float4 hv = ((const float4*)h)[s * 32 + lane];
    red_add_v4(&acc[d * DDIM + lane * 4], w * hv.x, w * hv.y, w * hv.z, w * hv.w);
}

// ---------------- final linear ----------------
__global__ __launch_bounds__(256) void final_linear(
    const float* __restrict__ h, const float* __restrict__ Wl,
    const float* __restrict__ bl, float* __restrict__ out)
{
    int warp = (blockIdx.x * blockDim.x + threadIdx.x) >> 5;
    int lane = threadIdx.x & 31;
    if (warp >= N_NODES) return;
    float4 hv = ((const float4*)h)[warp * 32 + lane];
    float4 wv = ((const float4*)Wl)[lane];
    float s = hv.x * wv.x + hv.y * wv.y + hv.z * wv.z + hv.w * wv.w;
#pragma unroll
    for (int off = 16; off > 0; off >>= 1)
        s += __shfl_down_sync(0xffffffffu, s, off);
    if (lane == 0) out[warp] = s + bl[0];
}

// ---------------- launcher ----------------
extern "C" void kernel_launch(void* const* d_in, const int* in_sizes, int n_in,
                              void* d_out, int out_size)
{
    const float* x   = (const float*)d_in[0];
    const int*   ei  = (const int*)d_in[1];
    const float* Wg  = (const float*)d_in[2];
    const float* as  = (const float*)d_in[3];
    const float* ad  = (const float*)d_in[4];
    const float* bg  = (const float*)d_in[5];
    const float* Wih = (const float*)d_in[6];
    const float* Whh = (const float*)d_in[7];
    const float* bih = (const float*)d_in[8];
    const float* bhh = (const float*)d_in[9];
    const float* Wl  = (const float*)d_in[10];
    const float* bl  = (const float*)d_in[11];
    float* out = (float*)d_out;

    float *h_feat, *alS, *alD, *denom, *acc, *ghB, *hstate, *h32, *WihT, *WhhT;
    cudaGetSymbolAddress((void**)&h_feat, d_h_feat);
    cudaGetSymbolAddress((void**)&alS,    d_alS);
    cudaGetSymbolAddress((void**)&alD,    d_alD);
    cudaGetSymbolAddress((void**)&denom,  d_denom);
    cudaGetSymbolAddress((void**)&acc,    d_acc);
    cudaGetSymbolAddress((void**)&ghB,    d_ghbuf);
    cudaGetSymbolAddress((void**)&hstate, d_hstate);
    cudaGetSymbolAddress((void**)&h32,    d_h32);
    cudaGetSymbolAddress((void**)&WihT,   d_WihT);
    cudaGetSymbolAddress((void**)&WhhT,   d_WhhT);

    cudaFuncSetAttribute(gemm_tf32_pipe,
                         cudaFuncAttributeMaxDynamicSharedMemorySize, PIPE_SMEM_BYTES);
    cudaFuncSetAttribute(gru_fused,
                         cudaFuncAttributeMaxDynamicSharedMemorySize, GF_SMEM_BYTES);

    const int GX = (N_NODES + 127) / 128;   // 391
    const int GF = (N_NODES + 63) / 64;     // 782

    zero_kernel<<<(ND + 255) / 256, 256>>>(hstate, h32, ND);
    transpose_w<<<(D3 * DDIM + 255) / 256, 256>>>(Wih, WihT);
    transpose_w<<<(D3 * DDIM + 255) / 256, 256>>>(Whh, WhhT);

    for (int t = 0; t < T_STEPS; t++) {
        // 1) h = x_t @ W_gat (+ fused attention logits + self-loop init)
        gemm_att<<<GX, 256>>>(x + (long)t * F_IN, T_STEPS * F_IN, N_NODES, Wg, h_feat,
                              as, ad, alS, alD, denom, acc);

        // 2) edge pass (unnormalized softmax accumulation)
        const int* src = ei + (long)t * 2 * E_EDGES;
        const int* dst = src + E_EDGES;
        edge_kernel<<<(E_EDGES * 32 + 255) / 256, 256>>>(src, dst, alS, alD, h_feat, denom, acc);

        // 3) gh = h32 @ WhhT + b_hh
        gemm_tf32_pipe<<<dim3(GX, 3), 256, PIPE_SMEM_BYTES>>>(h32, N_NODES, WhhT, D3, bhh, ghB);

        // 4) fused: finalize + gi GEMM (3 gates) + GRU gates -> h, h32
        gru_fused<<<GF, 256, GF_SMEM_BYTES>>>(acc, denom, bg, WihT, bih, ghB,
                                              hstate, h32, N_NODES);
    }

    final_linear<<<(N_NODES * 32 + 255) / 256, 256>>>(hstate, Wl, bl, out);
}

// round 8
// speedup vs baseline: 1.3241x; 1.3241x over previous
#include <cuda_runtime.h>
#include <cuda_fp16.h>
#include <cstdint>

// Problem constants (fixed shapes)
#define N_NODES 50000
#define T_STEPS 12
#define F_IN    128
#define HEADS   4
#define DDIM    128
#define E_EDGES 800000
#define NEG_SLOPE 0.2f
#define D3      384

#define ND (N_NODES * DDIM)
#define NH (N_NODES * HEADS)

// ---------------- scratch (device globals) ----------------
__device__ __half d_Wg16[DDIM * F_IN];     // [n][k]
__device__ __half d_Wih16[D3 * DDIM];      // [n][k] (native row-major)
__device__ __half d_Whh16[D3 * DDIM];
__device__ float  d_h_feat[ND];
__device__ float  d_alS[NH];
__device__ float  d_alD[NH];
__device__ float  d_denom[NH];
__device__ float  d_acc[ND];
__device__ __half d_g16[ND];
__device__ float  d_gi[N_NODES * D3];
__device__ float  d_gh[N_NODES * D3];
__device__ float  d_hstate[ND];            // exact fp32 GRU state
__device__ __half d_h16[ND];               // fp16 copy (GEMM input)

#define ROWH 136                            // halves per smem row (pad)
#define TILEH (128 * ROWH)                  // halves per 128-row tile
#define GEMM_SMEM_BYTES (2 * TILEH * 2)
#define ATT_SMEM_BYTES  (2 * TILEH * 2 + 2 * 512 * 4)

__device__ __forceinline__ void mma16816(float* c, const uint32_t* a, const uint32_t* b) {
    asm volatile(
        "mma.sync.aligned.m16n8k16.row.col.f32.f16.f16.f32 "
        "{%0,%1,%2,%3}, {%4,%5,%6,%7}, {%8,%9}, {%0,%1,%2,%3};\n"
        : "+f"(c[0]), "+f"(c[1]), "+f"(c[2]), "+f"(c[3])
        : "r"(a[0]), "r"(a[1]), "r"(a[2]), "r"(a[3]), "r"(b[0]), "r"(b[1]));
}

__device__ __forceinline__ void cp_async16(uint32_t saddr, const void* gptr, int srcsize) {
    asm volatile("cp.async.cg.shared.global [%0], [%1], 16, %2;"
                 :: "r"(saddr), "l"(gptr), "r"(srcsize));
}

// ---------------- utility kernels ----------------
__global__ void zero_kernel(float* p, __half* q, int n) {
    int i = blockIdx.x * blockDim.x + threadIdx.x;
    if (i < n) { p[i] = 0.0f; q[i] = __float2half(0.0f); }
}

__global__ void conv_w_nk(const float* __restrict__ W, __half* __restrict__ W16, int n) {
    int i = blockIdx.x * blockDim.x + threadIdx.x;
    if (i < n) W16[i] = __float2half_rn(W[i]);
}

// Wg [k][n] row-major -> Wg16 [n][k]
__global__ void conv_wg(const float* __restrict__ Wg, __half* __restrict__ Wg16) {
    int i = blockIdx.x * blockDim.x + threadIdx.x;
    if (i < DDIM * F_IN) {
        int n = i >> 7, k = i & 127;
        Wg16[i] = __float2half_rn(Wg[k * DDIM + n]);
    }
}

// ---------------- fp16 GEMM + fused attention-logit epilogue ----------------
// A fp32 [M][lda] converted to fp16 in smem. W = Wg16 [128][128] n-major.
__global__ __launch_bounds__(256, 2) void gemm_att(
    const float* __restrict__ A, int lda, int M,
    const __half* __restrict__ Wt,
    float* __restrict__ C,
    const float* __restrict__ a_src, const float* __restrict__ a_dst,
    float* __restrict__ alS, float* __restrict__ alD,
    float* __restrict__ denom, float* __restrict__ acc)
{
    extern __shared__ __half smh[];
    __half* As = smh;                 // [128][ROWH]
    __half* Ws = smh + TILEH;         // [128][ROWH]
    float* sS = (float*)(smh + 2 * TILEH);   // [512]
    float* sD = sS + 512;

    const int tid  = threadIdx.x;
    const int lane = tid & 31;
    const int wid  = tid >> 5;
    const int wm   = (wid & 3) * 32;
    const int wn   = (wid >> 2) * 64;
    const int row0 = blockIdx.x * 128;
    const int lq   = lane >> 2;
    const int lr   = lane & 3;

    if (tid < 256) { sS[tid] = 0.f; sS[tid + 256] = 0.f;
                     sD[tid] = 0.f; sD[tid + 256] = 0.f; }

    // W tile via cp.async (fp16, 128 rows x 256B)
    const uint32_t sW = (uint32_t)__cvta_generic_to_shared(Ws);
    {
        int ra = tid >> 4, c16 = tid & 15;
#pragma unroll
        for (int i = 0; i < 8; i++) {
            int r = ra + i * 16;
            cp_async16(sW + (uint32_t)((r * ROWH + c16 * 8) * 2),
                       &Wt[(long)r * 128 + c16 * 8], 16);
        }
        asm volatile("cp.async.commit_group;");
    }
    // A tile: LDG fp32 float4 -> cvt -> STS half4
    {
        int rb = tid >> 5, c4 = tid & 31;
#pragma unroll
        for (int i = 0; i < 16; i++) {
            int r = rb + i * 8;
            int gr = row0 + r;
            float4 v = make_float4(0.f, 0.f, 0.f, 0.f);
            if (gr < M) v = *(const float4*)&A[(long)gr * lda + c4 * 4];
            __half2 h0 = __floats2half2_rn(v.x, v.y);
            __half2 h1 = __floats2half2_rn(v.z, v.w);
            __half2* dp = (__half2*)&As[r * ROWH + c4 * 4];
            dp[0] = h0; dp[1] = h1;
        }
    }
    asm volatile("cp.async.wait_group 0;");
    __syncthreads();

    float cacc[2][8][4];
#pragma unroll
    for (int mf = 0; mf < 2; mf++)
#pragma unroll
        for (int nf = 0; nf < 8; nf++)
#pragma unroll
            for (int q = 0; q < 4; q++) cacc[mf][nf][q] = 0.0f;

#pragma unroll
    for (int ks = 0; ks < 8; ks++) {
        const int kh = ks * 16;
        uint32_t af[2][4];
#pragma unroll
        for (int mf = 0; mf < 2; mf++) {
            int rw = wm + mf * 16 + lq;
            af[mf][0] = *(const uint32_t*)&As[rw * ROWH + kh + 2 * lr];
            af[mf][1] = *(const uint32_t*)&As[(rw + 8) * ROWH + kh + 2 * lr];
            af[mf][2] = *(const uint32_t*)&As[rw * ROWH + kh + 8 + 2 * lr];
            af[mf][3] = *(const uint32_t*)&As[(rw + 8) * ROWH + kh + 8 + 2 * lr];
        }
#pragma unroll
        for (int nf = 0; nf < 8; nf++) {
            int cc = wn + nf * 8 + lq;
            uint32_t bf[2];
            bf[0] = *(const uint32_t*)&Ws[cc * ROWH + kh + 2 * lr];
            bf[1] = *(const uint32_t*)&Ws[cc * ROWH + kh + 8 + 2 * lr];
#pragma unroll
            for (int mf = 0; mf < 2; mf++)
                mma16816(cacc[mf][nf], af[mf], bf);
        }
    }

    // ===== fused attention epilogue (unchanged numerics) =====
    __syncthreads();
    {
        float aSv[8][2], aDv[8][2];
#pragma unroll
        for (int nf = 0; nf < 8; nf++) {
            int cc = wn + nf * 8 + lr * 2;
            aSv[nf][0] = a_src[cc];     aSv[nf][1] = a_src[cc + 1];
            aDv[nf][0] = a_dst[cc];     aDv[nf][1] = a_dst[cc + 1];
        }
#pragma unroll
        for (int mf = 0; mf < 2; mf++) {
#pragma unroll
            for (int half = 0; half < 2; half++) {
                int lrow = wm + mf * 16 + lq + half * 8;
                int h0 = wn >> 5;
                float pS0 = 0.f, pD0 = 0.f, pS1 = 0.f, pD1 = 0.f;
#pragma unroll
                for (int nf = 0; nf < 4; nf++) {
                    float v0 = cacc[mf][nf][half * 2], v1 = cacc[mf][nf][half * 2 + 1];
                    pS0 += v0 * aSv[nf][0] + v1 * aSv[nf][1];
                    pD0 += v0 * aDv[nf][0] + v1 * aDv[nf][1];
                }
#pragma unroll
                for (int nf = 4; nf < 8; nf++) {
                    float v0 = cacc[mf][nf][half * 2], v1 = cacc[mf][nf][half * 2 + 1];
                    pS1 += v0 * aSv[nf][0] + v1 * aSv[nf][1];
                    pD1 += v0 * aDv[nf][0] + v1 * aDv[nf][1];
                }
                atomicAdd(&sS[lrow * HEADS + h0], pS0);
                atomicAdd(&sD[lrow * HEADS + h0], pD0);
                atomicAdd(&sS[lrow * HEADS + h0 + 1], pS1);
                atomicAdd(&sD[lrow * HEADS + h0 + 1], pD1);
            }
        }
    }
    __syncthreads();
    for (int i = tid; i < 128 * HEADS; i += 256) {
        int lrow = i >> 2;
        int gr = row0 + lrow;
        if (gr < M) {
            float sg = sS[i], dg = sD[i];
            float v = sg + dg;
            float e = v > 0.0f ? v : NEG_SLOPE * v;
            float w = __expf(e);
            alS[(long)gr * HEADS + (i & 3)] = sg;
            alD[(long)gr * HEADS + (i & 3)] = dg;
            denom[(long)gr * HEADS + (i & 3)] = w;
            sD[i] = w;
        }
    }
    __syncthreads();
#pragma unroll
    for (int mf = 0; mf < 2; mf++) {
        int lrow = wm + mf * 16 + lq;
#pragma unroll
        for (int nf = 0; nf < 8; nf++) {
            int cc = wn + nf * 8 + lr * 2;
            int head = cc >> 5;
            int r_b = row0 + lrow;
            if (r_b < M) {
                float w = sD[lrow * HEADS + head];
                float2 o = make_float2(cacc[mf][nf][0], cacc[mf][nf][1]);
                *(float2*)&C[(long)r_b * DDIM + cc] = o;
                *(float2*)&acc[(long)r_b * DDIM + cc] = make_float2(o.x * w, o.y * w);
            }
            if (r_b + 8 < M) {
                float w = sD[(lrow + 8) * HEADS + head];
                float2 o = make_float2(cacc[mf][nf][2], cacc[mf][nf][3]);
                *(float2*)&C[(long)(r_b + 8) * DDIM + cc] = o;
                *(float2*)&acc[(long)(r_b + 8) * DDIM + cc] = make_float2(o.x * w, o.y * w);
            }
        }
    }
}

// ---------------- plain fp16 GEMM: C[M][NO] = A16[M][128] @ W16t[NO][128]^T + bias ----------------
__global__ __launch_bounds__(256, 2) void gemm_f16(
    const __half* __restrict__ A, int M,
    const __half* __restrict__ Wt,      // [NO][128] n-major
    const float* __restrict__ bias,
    float* __restrict__ C, int NO)
{
    extern __shared__ __half smh[];
    __half* As = smh;
    __half* Ws = smh + TILEH;

    const int tid  = threadIdx.x;
    const int lane = tid & 31;
    const int wid  = tid >> 5;
    const int wm   = (wid & 3) * 32;
    const int wn   = (wid >> 2) * 64;
    const int row0 = blockIdx.x * 128;
    const int c0   = blockIdx.y * 128;
    const int lq   = lane >> 2;
    const int lr   = lane & 3;

    const uint32_t sA = (uint32_t)__cvta_generic_to_shared(As);
    const uint32_t sW = (uint32_t)__cvta_generic_to_shared(Ws);
    {
        int ra = tid >> 4, c16 = tid & 15;
#pragma unroll
        for (int i = 0; i < 8; i++) {
            int r = ra + i * 16;
            int gr = row0 + r;
            const __half* gp = &A[(long)(gr < M ? gr : 0) * 128 + c16 * 8];
            cp_async16(sA + (uint32_t)((r * ROWH + c16 * 8) * 2), gp, gr < M ? 16 : 0);
        }
#pragma unroll
        for (int i = 0; i < 8; i++) {
            int r = ra + i * 16;
            cp_async16(sW + (uint32_t)((r * ROWH + c16 * 8) * 2),
                       &Wt[(long)(c0 + r) * 128 + c16 * 8], 16);
        }
        asm volatile("cp.async.commit_group;");
        asm volatile("cp.async.wait_group 0;");
    }
    __syncthreads();

    float cacc[2][8][4];
#pragma unroll
    for (int mf = 0; mf < 2; mf++)
#pragma unroll
        for (int nf = 0; nf < 8; nf++)
#pragma unroll
            for (int q = 0; q < 4; q++) cacc[mf][nf][q] = 0.0f;

#pragma unroll
    for (int ks = 0; ks < 8; ks++) {
        const int kh = ks * 16;
        uint32_t af[2][4];
#pragma unroll
        for (int mf = 0; mf < 2; mf++) {
            int rw = wm + mf * 16 + lq;
            af[mf][0] = *(const uint32_t*)&As[rw * ROWH + kh + 2 * lr];
            af[mf][1] = *(const uint32_t*)&As[(rw + 8) * ROWH + kh + 2 * lr];
            af[mf][2] = *(const uint32_t*)&As[rw * ROWH + kh + 8 + 2 * lr];
            af[mf][3] = *(const uint32_t*)&As[(rw + 8) * ROWH + kh + 8 + 2 * lr];
        }
#pragma unroll
        for (int nf = 0; nf < 8; nf++) {
            int cc = wn + nf * 8 + lq;
            uint32_t bf[2];
            bf[0] = *(const uint32_t*)&Ws[cc * ROWH + kh + 2 * lr];
            bf[1] = *(const uint32_t*)&Ws[cc * ROWH + kh + 8 + 2 * lr];
#pragma unroll
            for (int mf = 0; mf < 2; mf++)
                mma16816(cacc[mf][nf], af[mf], bf);
        }
    }

#pragma unroll
    for (int mf = 0; mf < 2; mf++) {
        int r_b = row0 + wm + mf * 16 + lq;
#pragma unroll
        for (int nf = 0; nf < 8; nf++) {
            int cc = c0 + wn + nf * 8 + lr * 2;
            float b0 = bias[cc];
            float b1 = bias[cc + 1];
            if (r_b < M)
                *(float2*)&C[(long)r_b * NO + cc] =
                    make_float2(cacc[mf][nf][0] + b0, cacc[mf][nf][1] + b1);
            if (r_b + 8 < M)
                *(float2*)&C[(long)(r_b + 8) * NO + cc] =
                    make_float2(cacc[mf][nf][2] + b0, cacc[mf][nf][3] + b1);
        }
    }
}

// ---------------- edge pass ----------------
__device__ __forceinline__ void red_add_v4(float* addr, float a, float b, float c, float d) {
    asm volatile("red.global.add.v4.f32 [%0], {%1,%2,%3,%4};"
                 :: "l"(addr), "f"(a), "f"(b), "f"(c), "f"(d) : "memory");
}

__global__ __launch_bounds__(256) void edge_kernel(
    const int* __restrict__ src_arr, const int* __restrict__ dst_arr,
    const float* __restrict__ alS, const float* __restrict__ alD,
    const float* __restrict__ h,
    float* __restrict__ denom, float* __restrict__ acc)
{
    long gw = (long)blockIdx.x * (blockDim.x >> 5) + (threadIdx.x >> 5);
    if (gw >= E_EDGES) return;
    int lane = threadIdx.x & 31;
    int head = lane >> 3;

    int s = src_arr[gw];
    int d = dst_arr[gw];

    float v = alS[s * HEADS + head] + alD[d * HEADS + head];
    float e = v > 0.0f ? v : NEG_SLOPE * v;
    float w = __expf(e);

    if ((lane & 7) == 0) atomicAdd(&denom[d * HEADS + head], w);

    float4 hv = ((const float4*)h)[s * 32 + lane];
    red_add_v4(&acc[d * DDIM + lane * 4], w * hv.x, w * hv.y, w * hv.z, w * hv.w);
}

// ---------------- finalize GAT: g16 = fp16(relu(acc/denom + bg)) ----------------
__global__ void finalize_gat(
    const float* __restrict__ acc, const float* __restrict__ denom,
    const float* __restrict__ bg, __half* __restrict__ g16)
{
    int idx = blockIdx.x * blockDim.x + threadIdx.x;   // over N*32 float4s
    if (idx >= N_NODES * 32) return;
    int n = idx >> 5;
    int c4 = idx & 31;
    int head = c4 >> 3;
    float inv = 1.0f / (denom[n * HEADS + head] + 1e-16f);
    float4 a = ((const float4*)acc)[idx];
    float4 b = ((const float4*)bg)[c4];
    __half2 p0 = __floats2half2_rn(fmaxf(a.x * inv + b.x, 0.0f),
                                   fmaxf(a.y * inv + b.y, 0.0f));
    __half2 p1 = __floats2half2_rn(fmaxf(a.z * inv + b.z, 0.0f),
                                   fmaxf(a.w * inv + b.w, 0.0f));
    ((__half2*)g16)[idx * 2] = p0;
    ((__half2*)g16)[idx * 2 + 1] = p1;
}

// ---------------- GRU gates: h = (1-z)*n + z*h; also fp16 copy ----------------
__global__ void gru_gates(
    const float* __restrict__ gi, const float* __restrict__ gh,
    float* __restrict__ h, __half* __restrict__ h16)
{
    int idx = blockIdx.x * blockDim.x + threadIdx.x;   // over N*32 float4s
    if (idx >= N_NODES * 32) return;
    int n = idx >> 5;
    long base = (long)n * D3 + (idx & 31) * 4;
    float4 ir = *(const float4*)&gi[base];
    float4 hr = *(const float4*)&gh[base];
    float4 iz = *(const float4*)&gi[base + 128];
    float4 hz = *(const float4*)&gh[base + 128];
    float4 in_ = *(const float4*)&gi[base + 256];
    float4 hn = *(const float4*)&gh[base + 256];
    float4 hv = ((const float4*)h)[idx];
    float4 ho;
#pragma unroll
    for (int q = 0; q < 4; q++) {
        float irf = (&ir.x)[q], hrf = (&hr.x)[q];
        float izf = (&iz.x)[q], hzf = (&hz.x)[q];
        float inf = (&in_.x)[q], hnf = (&hn.x)[q];
        float hvf = (&hv.x)[q];
        float r = 1.0f / (1.0f + __expf(-(irf + hrf)));
        float z = 1.0f / (1.0f + __expf(-(izf + hzf)));
        float nn = tanhf(inf + r * hnf);
        (&ho.x)[q] = (1.0f - z) * nn + z * hvf;
    }
    ((float4*)h)[idx] = ho;
    ((__half2*)h16)[idx * 2]     = __floats2half2_rn(ho.x, ho.y);
    ((__half2*)h16)[idx * 2 + 1] = __floats2half2_rn(ho.z, ho.w);
}

// ---------------- final linear ----------------
__global__ __launch_bounds__(256) void final_linear(
    const float* __restrict__ h, const float* __restrict__ Wl,
    const float* __restrict__ bl, float* __restrict__ out)
{
    int warp = (blockIdx.x * blockDim.x + threadIdx.x) >> 5;
    int lane = threadIdx.x & 31;
    if (warp >= N_NODES) return;
    float4 hv = ((const float4*)h)[warp * 32 + lane];
    float4 wv = ((const float4*)Wl)[lane];
    float s = hv.x * wv.x + hv.y * wv.y + hv.z * wv.z + hv.w * wv.w;
#pragma unroll
    for (int off = 16; off > 0; off >>= 1)
        s += __shfl_down_sync(0xffffffffu, s, off);
    if (lane == 0) out[warp] = s + bl[0];
}

// ---------------- launcher ----------------
extern "C" void kernel_launch(void* const* d_in, const int* in_sizes, int n_in,
                              void* d_out, int out_size)
{
    const float* x   = (const float*)d_in[0];
    const int*   ei  = (const int*)d_in[1];
    const float* Wg  = (const float*)d_in[2];
    const float* as  = (const float*)d_in[3];
    const float* ad  = (const float*)d_in[4];
    const float* bg  = (const float*)d_in[5];
    const float* Wih = (const float*)d_in[6];
    const float* Whh = (const float*)d_in[7];
    const float* bih = (const float*)d_in[8];
    const float* bhh = (const float*)d_in[9];
    const float* Wl  = (const float*)d_in[10];
    const float* bl  = (const float*)d_in[11];
    float* out = (float*)d_out;

    float *h_feat, *alS, *alD, *denom, *acc, *gi, *gh, *hstate;
    __half *Wg16, *Wih16, *Whh16, *g16, *h16;
    cudaGetSymbolAddress((void**)&h_feat, d_h_feat);
    cudaGetSymbolAddress((void**)&alS,    d_alS);
    cudaGetSymbolAddress((void**)&alD,    d_alD);
    cudaGetSymbolAddress((void**)&denom,  d_denom);
    cudaGetSymbolAddress((void**)&acc,    d_acc);
    cudaGetSymbolAddress((void**)&gi,     d_gi);
    cudaGetSymbolAddress((void**)&gh,     d_gh);
    cudaGetSymbolAddress((void**)&hstate, d_hstate);
    cudaGetSymbolAddress((void**)&Wg16,   d_Wg16);
    cudaGetSymbolAddress((void**)&Wih16,  d_Wih16);
    cudaGetSymbolAddress((void**)&Whh16,  d_Whh16);
    cudaGetSymbolAddress((void**)&g16,    d_g16);
    cudaGetSymbolAddress((void**)&h16,    d_h16);

    cudaFuncSetAttribute(gemm_att,
                         cudaFuncAttributeMaxDynamicSharedMemorySize, ATT_SMEM_BYTES);
    cudaFuncSetAttribute(gemm_f16,
                         cudaFuncAttributeMaxDynamicSharedMemorySize, GEMM_SMEM_BYTES);

    const int GX = (N_NODES + 127) / 128;   // 391

    // prologue: zero state, convert weights to fp16
    zero_kernel<<<(ND + 255) / 256, 256>>>(hstate, h16, ND);
    conv_wg<<<(DDIM * F_IN + 255) / 256, 256>>>(Wg, Wg16);
    conv_w_nk<<<(D3 * DDIM + 255) / 256, 256>>>(Wih, Wih16, D3 * DDIM);
    conv_w_nk<<<(D3 * DDIM + 255) / 256, 256>>>(Whh, Whh16, D3 * DDIM);

    for (int t = 0; t < T_STEPS; t++) {
        // 1) h = x_t @ W_gat (+ fused attention logits + self-loop init)
        gemm_att<<<GX, 256, ATT_SMEM_BYTES>>>(
            x + (long)t * F_IN, T_STEPS * F_IN, N_NODES, Wg16, h_feat,
            as, ad, alS, alD, denom, acc);

        // 2) edge pass (unnormalized softmax accumulation)
        const int* src = ei + (long)t * 2 * E_EDGES;
        const int* dst = src + E_EDGES;
        edge_kernel<<<(E_EDGES * 32 + 255) / 256, 256>>>(src, dst, alS, alD, h_feat, denom, acc);

        // 3) g16 = fp16(relu(acc/denom + b_gat))
        finalize_gat<<<(N_NODES * 32 + 255) / 256, 256>>>(acc, denom, bg, g16);

        // 4) gi = g16 @ Wih^T + b_ih ; gh = h16 @ Whh^T + b_hh
        gemm_f16<<<dim3(GX, 3), 256, GEMM_SMEM_BYTES>>>(g16, N_NODES, Wih16, bih, gi, D3);
        gemm_f16<<<dim3(GX, 3), 256, GEMM_SMEM_BYTES>>>(h16, N_NODES, Whh16, bhh, gh, D3);

        // 5) GRU update (writes exact h + fp16 copy)
        gru_gates<<<(N_NODES * 32 + 255) / 256, 256>>>(gi, gh, hstate, h16);
    }

    final_linear<<<(N_NODES * 32 + 255) / 256, 256>>>(hstate, Wl, bl, out);
}

// round 10
// speedup vs baseline: 1.3543x; 1.0228x over previous
#include <cuda_runtime.h>
#include <cuda_fp16.h>
#include <cstdint>

// Problem constants (fixed shapes)
#define N_NODES 50000
#define T_STEPS 12
#define F_IN    128
#define HEADS   4
#define DDIM    128
#define E_EDGES 800000
#define NEG_SLOPE 0.2f
#define D3      384

#define ND (N_NODES * DDIM)
#define NH (N_NODES * HEADS)

// ---------------- scratch (device globals) ----------------
__device__ __half d_Wg16[DDIM * F_IN];     // [n][k]
__device__ __half d_Wih16[D3 * DDIM];      // [n][k] (native row-major)
__device__ __half d_Whh16[D3 * DDIM];
__device__ __half d_hf16[ND];              // GAT h features (edge gather only)
__device__ float  d_alS[NH];
__device__ float  d_alD[NH];
__device__ float  d_denom[NH];
__device__ float  d_acc[ND];
__device__ __half d_g16[ND];
__device__ float  d_gi[N_NODES * D3];
__device__ float  d_gh[N_NODES * D3];
__device__ float  d_hstate[ND];            // exact fp32 GRU state
__device__ __half d_h16[ND];               // fp16 copy (GEMM input)

#define ROWH 136                            // halves per smem row (pad)
#define TILEH (128 * ROWH)                  // halves per 128-row tile
#define GEMM_SMEM_BYTES (2 * TILEH * 2)
#define ATT_SMEM_BYTES  (2 * TILEH * 2 + 2 * 512 * 4)

__device__ __forceinline__ void mma16816(float* c, const uint32_t* a, const uint32_t* b) {
    asm volatile(
        "mma.sync.aligned.m16n8k16.row.col.f32.f16.f16.f32 "
        "{%0,%1,%2,%3}, {%4,%5,%6,%7}, {%8,%9}, {%0,%1,%2,%3};\n"
        : "+f"(c[0]), "+f"(c[1]), "+f"(c[2]), "+f"(c[3])
        : "r"(a[0]), "r"(a[1]), "r"(a[2]), "r"(a[3]), "r"(b[0]), "r"(b[1]));
}

__device__ __forceinline__ void cp_async16(uint32_t saddr, const void* gptr, int srcsize) {
    asm volatile("cp.async.cg.shared.global [%0], [%1], 16, %2;"
                 :: "r"(saddr), "l"(gptr), "r"(srcsize));
}

__device__ __forceinline__ float tanh_fast(float x) {
    float r;
    asm("tanh.approx.f32 %0, %1;" : "=f"(r) : "f"(x));
    return r;
}

// ---------------- utility kernels ----------------
__global__ void zero_kernel(float* p, __half* q, int n) {
    int i = blockIdx.x * blockDim.x + threadIdx.x;
    if (i < n) { p[i] = 0.0f; q[i] = __float2half(0.0f); }
}

__global__ void conv_w_nk(const float* __restrict__ W, __half* __restrict__ W16, int n) {
    int i = blockIdx.x * blockDim.x + threadIdx.x;
    if (i < n) W16[i] = __float2half_rn(W[i]);
}

// Wg [k][n] row-major -> Wg16 [n][k]
__global__ void conv_wg(const float* __restrict__ Wg, __half* __restrict__ Wg16) {
    int i = blockIdx.x * blockDim.x + threadIdx.x;
    if (i < DDIM * F_IN) {
        int n = i >> 7, k = i & 127;
        Wg16[i] = __float2half_rn(Wg[k * DDIM + n]);
    }
}

// ---------------- fp16 GEMM + fused attention-logit epilogue ----------------
// A fp32 [M][lda] converted to fp16 in smem. W = Wg16 [128][128] n-major.
// Writes: hf16 (fp16 h features), alS/alD/denom, self-loop acc (fp32).
__global__ __launch_bounds__(256, 2) void gemm_att(
    const float* __restrict__ A, int lda, int M,
    const __half* __restrict__ Wt,
    __half* __restrict__ hf16,
    const float* __restrict__ a_src, const float* __restrict__ a_dst,
    float* __restrict__ alS, float* __restrict__ alD,
    float* __restrict__ denom, float* __restrict__ acc)
{
    extern __shared__ __half smh[];
    __half* As = smh;                 // [128][ROWH]
    __half* Ws = smh + TILEH;         // [128][ROWH]
    float* sS = (float*)(smh + 2 * TILEH);   // [512]
    float* sD = sS + 512;

    const int tid  = threadIdx.x;
    const int lane = tid & 31;
    const int wid  = tid >> 5;
    const int wm   = (wid & 3) * 32;
    const int wn   = (wid >> 2) * 64;
    const int row0 = blockIdx.x * 128;
    const int lq   = lane >> 2;
    const int lr   = lane & 3;

    if (tid < 256) { sS[tid] = 0.f; sS[tid + 256] = 0.f;
                     sD[tid] = 0.f; sD[tid + 256] = 0.f; }

    // W tile via cp.async (fp16, 128 rows x 256B)
    const uint32_t sW = (uint32_t)__cvta_generic_to_shared(Ws);
    {
        int ra = tid >> 4, c16 = tid & 15;
#pragma unroll
        for (int i = 0; i < 8; i++) {
            int r = ra + i * 16;
            cp_async16(sW + (uint32_t)((r * ROWH + c16 * 8) * 2),
                       &Wt[(long)r * 128 + c16 * 8], 16);
        }
        asm volatile("cp.async.commit_group;");
    }
    // A tile: LDG fp32 float4 -> cvt -> STS half4
    {
        int rb = tid >> 5, c4 = tid & 31;
#pragma unroll
        for (int i = 0; i < 16; i++) {
            int r = rb + i * 8;
            int gr = row0 + r;
            float4 v = make_float4(0.f, 0.f, 0.f, 0.f);
            if (gr < M) v = *(const float4*)&A[(long)gr * lda + c4 * 4];
            __half2 h0 = __floats2half2_rn(v.x, v.y);
            __half2 h1 = __floats2half2_rn(v.z, v.w);
            __half2* dp = (__half2*)&As[r * ROWH + c4 * 4];
            dp[0] = h0; dp[1] = h1;
        }
    }
    asm volatile("cp.async.wait_group 0;");
    __syncthreads();

    float cacc[2][8][4];
#pragma unroll
    for (int mf = 0; mf < 2; mf++)
#pragma unroll
        for (int nf = 0; nf < 8; nf++)
#pragma unroll
            for (int q = 0; q < 4; q++) cacc[mf][nf][q] = 0.0f;

#pragma unroll
    for (int ks = 0; ks < 8; ks++) {
        const int kh = ks * 16;
        uint32_t af[2][4];
#pragma unroll
        for (int mf = 0; mf < 2; mf++) {
            int rw = wm + mf * 16 + lq;
            af[mf][0] = *(const uint32_t*)&As[rw * ROWH + kh + 2 * lr];
            af[mf][1] = *(const uint32_t*)&As[(rw + 8) * ROWH + kh + 2 * lr];
            af[mf][2] = *(const uint32_t*)&As[rw * ROWH + kh + 8 + 2 * lr];
            af[mf][3] = *(const uint32_t*)&As[(rw + 8) * ROWH + kh + 8 + 2 * lr];
        }
#pragma unroll
        for (int nf = 0; nf < 8; nf++) {
            int cc = wn + nf * 8 + lq;
            uint32_t bf[2];
            bf[0] = *(const uint32_t*)&Ws[cc * ROWH + kh + 2 * lr];
            bf[1] = *(const uint32_t*)&Ws[cc * ROWH + kh + 8 + 2 * lr];
#pragma unroll
            for (int mf = 0; mf < 2; mf++)
                mma16816(cacc[mf][nf], af[mf], bf);
        }
    }

    // ===== fused attention epilogue =====
    __syncthreads();
    {
        float aSv[8][2], aDv[8][2];
#pragma unroll
        for (int nf = 0; nf < 8; nf++) {
            int cc = wn + nf * 8 + lr * 2;
            aSv[nf][0] = a_src[cc];     aSv[nf][1] = a_src[cc + 1];
            aDv[nf][0] = a_dst[cc];     aDv[nf][1] = a_dst[cc + 1];
        }
#pragma unroll
        for (int mf = 0; mf < 2; mf++) {
#pragma unroll
            for (int half = 0; half < 2; half++) {
                int lrow = wm + mf * 16 + lq + half * 8;
                int h0 = wn >> 5;
                float pS0 = 0.f, pD0 = 0.f, pS1 = 0.f, pD1 = 0.f;
#pragma unroll
                for (int nf = 0; nf < 4; nf++) {
                    float v0 = cacc[mf][nf][half * 2], v1 = cacc[mf][nf][half * 2 + 1];
                    pS0 += v0 * aSv[nf][0] + v1 * aSv[nf][1];
                    pD0 += v0 * aDv[nf][0] + v1 * aDv[nf][1];
                }
#pragma unroll
                for (int nf = 4; nf < 8; nf++) {
                    float v0 = cacc[mf][nf][half * 2], v1 = cacc[mf][nf][half * 2 + 1];
                    pS1 += v0 * aSv[nf][0] + v1 * aSv[nf][1];
                    pD1 += v0 * aDv[nf][0] + v1 * aDv[nf][1];
                }
                atomicAdd(&sS[lrow * HEADS + h0], pS0);
                atomicAdd(&sD[lrow * HEADS + h0], pD0);
                atomicAdd(&sS[lrow * HEADS + h0 + 1], pS1);
                atomicAdd(&sD[lrow * HEADS + h0 + 1], pD1);
            }
        }
    }
    __syncthreads();
    for (int i = tid; i < 128 * HEADS; i += 256) {
        int lrow = i >> 2;
        int gr = row0 + lrow;
        if (gr < M) {
            float sg = sS[i], dg = sD[i];
            float v = sg + dg;
            float e = v > 0.0f ? v : NEG_SLOPE * v;
            float w = __expf(e);
            alS[(long)gr * HEADS + (i & 3)] = sg;
            alD[(long)gr * HEADS + (i & 3)] = dg;
            denom[(long)gr * HEADS + (i & 3)] = w;
            sD[i] = w;
        }
    }
    __syncthreads();
#pragma unroll
    for (int mf = 0; mf < 2; mf++) {
        int lrow = wm + mf * 16 + lq;
#pragma unroll
        for (int nf = 0; nf < 8; nf++) {
            int cc = wn + nf * 8 + lr * 2;
            int head = cc >> 5;
            int r_b = row0 + lrow;
            if (r_b < M) {
                float w = sD[lrow * HEADS + head];
                float2 o = make_float2(cacc[mf][nf][0], cacc[mf][nf][1]);
                *(__half2*)&hf16[(long)r_b * DDIM + cc] = __floats2half2_rn(o.x, o.y);
                *(float2*)&acc[(long)r_b * DDIM + cc] = make_float2(o.x * w, o.y * w);
            }
            if (r_b + 8 < M) {
                float w = sD[(lrow + 8) * HEADS + head];
                float2 o = make_float2(cacc[mf][nf][2], cacc[mf][nf][3]);
                *(__half2*)&hf16[(long)(r_b + 8) * DDIM + cc] = __floats2half2_rn(o.x, o.y);
                *(float2*)&acc[(long)(r_b + 8) * DDIM + cc] = make_float2(o.x * w, o.y * w);
            }
        }
    }
}

// ---------------- dual fp16 GEMM: gi = g16@Wih^T + bih ; gh = h16@Whh^T + bhh ----------------
// grid (GX, 6): y/3 selects (gi|gh), y%3 selects 128-col gate chunk.
__global__ __launch_bounds__(256, 2) void gemm_f16_dual(
    const __half* __restrict__ Ag, const __half* __restrict__ Ah, int M,
    const __half* __restrict__ Wih, const __half* __restrict__ Whh,
    const float* __restrict__ bih, const float* __restrict__ bhh,
    float* __restrict__ Cgi, float* __restrict__ Cgh)
{
    extern __shared__ __half smh[];
    __half* As = smh;
    __half* Ws = smh + TILEH;

    const int which = blockIdx.y / 3;
    const int c0    = (blockIdx.y % 3) * 128;
    const __half* A  = which ? Ah : Ag;
    const __half* Wt = which ? Whh : Wih;
    const float* bias = which ? bhh : bih;
    float* C = which ? Cgh : Cgi;

    const int tid  = threadIdx.x;
    const int lane = tid & 31;
    const int wid  = tid >> 5;
    const int wm   = (wid & 3) * 32;
    const int wn   = (wid >> 2) * 64;
    const int row0 = blockIdx.x * 128;
    const int lq   = lane >> 2;
    const int lr   = lane & 3;

    const uint32_t sA = (uint32_t)__cvta_generic_to_shared(As);
    const uint32_t sW = (uint32_t)__cvta_generic_to_shared(Ws);
    {
        int ra = tid >> 4, c16 = tid & 15;
#pragma unroll
        for (int i = 0; i < 8; i++) {
            int r = ra + i * 16;
            int gr = row0 + r;
            const __half* gp = &A[(long)(gr < M ? gr : 0) * 128 + c16 * 8];
            cp_async16(sA + (uint32_t)((r * ROWH + c16 * 8) * 2), gp, gr < M ? 16 : 0);
        }
#pragma unroll
        for (int i = 0; i < 8; i++) {
            int r = ra + i * 16;
            cp_async16(sW + (uint32_t)((r * ROWH + c16 * 8) * 2),
                       &Wt[(long)(c0 + r) * 128 + c16 * 8], 16);
        }
        asm volatile("cp.async.commit_group;");
        asm volatile("cp.async.wait_group 0;");
    }
    __syncthreads();

    float cacc[2][8][4];
#pragma unroll
    for (int mf = 0; mf < 2; mf++)
#pragma unroll
        for (int nf = 0; nf < 8; nf++)
#pragma unroll
            for (int q = 0; q < 4; q++) cacc[mf][nf][q] = 0.0f;

#pragma unroll
    for (int ks = 0; ks < 8; ks++) {
        const int kh = ks * 16;
        uint32_t af[2][4];
#pragma unroll
        for (int mf = 0; mf < 2; mf++) {
            int rw = wm + mf * 16 + lq;
            af[mf][0] = *(const uint32_t*)&As[rw * ROWH + kh + 2 * lr];
            af[mf][1] = *(const uint32_t*)&As[(rw + 8) * ROWH + kh + 2 * lr];
            af[mf][2] = *(const uint32_t*)&As[rw * ROWH + kh + 8 + 2 * lr];
            af[mf][3] = *(const uint32_t*)&As[(rw + 8) * ROWH + kh + 8 + 2 * lr];
        }
#pragma unroll
        for (int nf = 0; nf < 8; nf++) {
            int cc = wn + nf * 8 + lq;
            uint32_t bf[2];
            bf[0] = *(const uint32_t*)&Ws[cc * ROWH + kh + 2 * lr];
            bf[1] = *(const uint32_t*)&Ws[cc * ROWH + kh + 8 + 2 * lr];
#pragma unroll
            for (int mf = 0; mf < 2; mf++)
                mma16816(cacc[mf][nf], af[mf], bf);
        }
    }

#pragma unroll
    for (int mf = 0; mf < 2; mf++) {
        int r_b = row0 + wm + mf * 16 + lq;
#pragma unroll
        for (int nf = 0; nf < 8; nf++) {
            int cc = c0 + wn + nf * 8 + lr * 2;
            float b0 = bias[cc];
            float b1 = bias[cc + 1];
            if (r_b < M)
                *(float2*)&C[(long)r_b * D3 + cc] =
                    make_float2(cacc[mf][nf][0] + b0, cacc[mf][nf][1] + b1);
            if (r_b + 8 < M)
                *(float2*)&C[(long)(r_b + 8) * D3 + cc] =
                    make_float2(cacc[mf][nf][2] + b0, cacc[mf][nf][3] + b1);
        }
    }
}

// ---------------- edge pass (fp16 gather, fp32 RED) ----------------
__device__ __forceinline__ void red_add_v4(float* addr, float a, float b, float c, float d) {
    asm volatile("red.global.add.v4.f32 [%0], {%1,%2,%3,%4};"
                 :: "l"(addr), "f"(a), "f"(b), "f"(c), "f"(d) : "memory");
}

__global__ __launch_bounds__(256) void edge_kernel(
    const int* __restrict__ src_arr, const int* __restrict__ dst_arr,
    const float* __restrict__ alS, const float* __restrict__ alD,
    const __half* __restrict__ hf16,
    float* __restrict__ denom, float* __restrict__ acc)
{
    long gw = (long)blockIdx.x * (blockDim.x >> 5) + (threadIdx.x >> 5);
    if (gw >= E_EDGES) return;
    int lane = threadIdx.x & 31;
    int head = lane >> 3;

    int s = src_arr[gw];
    int d = dst_arr[gw];

    float v = alS[s * HEADS + head] + alD[d * HEADS + head];
    float e = v > 0.0f ? v : NEG_SLOPE * v;
    float w = __expf(e);

    if ((lane & 7) == 0) atomicAdd(&denom[d * HEADS + head], w);

    // 4 halves per lane = 8B
    uint2 hv = ((const uint2*)hf16)[s * 32 + lane];
    float2 f0 = __half22float2(*(__half2*)&hv.x);
    float2 f1 = __half22float2(*(__half2*)&hv.y);
    red_add_v4(&acc[d * DDIM + lane * 4], w * f0.x, w * f0.y, w * f1.x, w * f1.y);
}

// ---------------- finalize GAT: g16 = fp16(relu(acc/denom + bg)) ----------------
__global__ void finalize_gat(
    const float* __restrict__ acc, const float* __restrict__ denom,
    const float* __restrict__ bg, __half* __restrict__ g16)
{
    int idx = blockIdx.x * blockDim.x + threadIdx.x;   // over N*32 float4s
    if (idx >= N_NODES * 32) return;
    int n = idx >> 5;
    int c4 = idx & 31;
    int head = c4 >> 3;
    float inv = 1.0f / (denom[n * HEADS + head] + 1e-16f);
    float4 a = ((const float4*)acc)[idx];
    float4 b = ((const float4*)bg)[c4];
    __half2 p0 = __floats2half2_rn(fmaxf(a.x * inv + b.x, 0.0f),
                                   fmaxf(a.y * inv + b.y, 0.0f));
    __half2 p1 = __floats2half2_rn(fmaxf(a.z * inv + b.z, 0.0f),
                                   fmaxf(a.w * inv + b.w, 0.0f));
    ((__half2*)g16)[idx * 2] = p0;
    ((__half2*)g16)[idx * 2 + 1] = p1;
}

// ---------------- GRU gates: h = (1-z)*n + z*h; also fp16 copy ----------------
__global__ void gru_gates(
    const float* __restrict__ gi, const float* __restrict__ gh,
    float* __restrict__ h, __half* __restrict__ h16)
{
    int idx = blockIdx.x * blockDim.x + threadIdx.x;   // over N*32 float4s
    if (idx >= N_NODES * 32) return;
    int n = idx >> 5;
    long base = (long)n * D3 + (idx & 31) * 4;
    float4 ir = *(const float4*)&gi[base];
    float4 hr = *(const float4*)&gh[base];
    float4 iz = *(const float4*)&gi[base + 128];
    float4 hz = *(const float4*)&gh[base + 128];
    float4 in_ = *(const float4*)&gi[base + 256];
    float4 hn = *(const float4*)&gh[base + 256];
    float4 hv = ((const float4*)h)[idx];
    float4 ho;
#pragma unroll
    for (int q = 0; q < 4; q++) {
        float irf = (&ir.x)[q], hrf = (&hr.x)[q];
        float izf = (&iz.x)[q], hzf = (&hz.x)[q];
        float inf = (&in_.x)[q], hnf = (&hn.x)[q];
        float hvf = (&hv.x)[q];
        float r = 1.0f / (1.0f + __expf(-(irf + hrf)));
        float z = 1.0f / (1.0f + __expf(-(izf + hzf)));
        float nn = tanh_fast(inf + r * hnf);
        (&ho.x)[q] = (1.0f - z) * nn + z * hvf;
    }
    ((float4*)h)[idx] = ho;
    ((__half2*)h16)[idx * 2]     = __floats2half2_rn(ho.x, ho.y);
    ((__half2*)h16)[idx * 2 + 1] = __floats2half2_rn(ho.z, ho.w);
}

// ---------------- final linear ----------------
__global__ __launch_bounds__(256) void final_linear(
    const float* __restrict__ h, const float* __restrict__ Wl,
    const float* __restrict__ bl, float* __restrict__ out)
{
    int warp = (blockIdx.x * blockDim.x + threadIdx.x) >> 5;
    int lane = threadIdx.x & 31;
    if (warp >= N_NODES) return;
    float4 hv = ((const float4*)h)[warp * 32 + lane];
    float4 wv = ((const float4*)Wl)[lane];
    float s = hv.x * wv.x + hv.y * wv.y + hv.z * wv.z + hv.w * wv.w;
#pragma unroll
    for (int off = 16; off > 0; off >>= 1)
        s += __shfl_down_sync(0xffffffffu, s, off);
    if (lane == 0) out[warp] = s + bl[0];
}

// ---------------- launcher ----------------
extern "C" void kernel_launch(void* const* d_in, const int* in_sizes, int n_in,
                              void* d_out, int out_size)
{
    const float* x   = (const float*)d_in[0];
    const int*   ei  = (const int*)d_in[1];
    const float* Wg  = (const float*)d_in[2];
    const float* as  = (const float*)d_in[3];
    const float* ad  = (const float*)d_in[4];
    const float* bg  = (const float*)d_in[5];
    const float* Wih = (const float*)d_in[6];
    const float* Whh = (const float*)d_in[7];
    const float* bih = (const float*)d_in[8];
    const float* bhh = (const float*)d_in[9];
    const float* Wl  = (const float*)d_in[10];
    const float* bl  = (const float*)d_in[11];
    float* out = (float*)d_out;

    float *alS, *alD, *denom, *acc, *gi, *gh, *hstate;
    __half *Wg16, *Wih16, *Whh16, *hf16, *g16, *h16;
    cudaGetSymbolAddress((void**)&alS,    d_alS);
    cudaGetSymbolAddress((void**)&alD,    d_alD);
    cudaGetSymbolAddress((void**)&denom,  d_denom);
    cudaGetSymbolAddress((void**)&acc,    d_acc);
    cudaGetSymbolAddress((void**)&gi,     d_gi);
    cudaGetSymbolAddress((void**)&gh,     d_gh);
    cudaGetSymbolAddress((void**)&hstate, d_hstate);
    cudaGetSymbolAddress((void**)&Wg16,   d_Wg16);
    cudaGetSymbolAddress((void**)&Wih16,  d_Wih16);
    cudaGetSymbolAddress((void**)&Whh16,  d_Whh16);
    cudaGetSymbolAddress((void**)&hf16,   d_hf16);
    cudaGetSymbolAddress((void**)&g16,    d_g16);
    cudaGetSymbolAddress((void**)&h16,    d_h16);

    cudaFuncSetAttribute(gemm_att,
                         cudaFuncAttributeMaxDynamicSharedMemorySize, ATT_SMEM_BYTES);
    cudaFuncSetAttribute(gemm_f16_dual,
                         cudaFuncAttributeMaxDynamicSharedMemorySize, GEMM_SMEM_BYTES);

    const int GX = (N_NODES + 127) / 128;   // 391

    // prologue: zero state, convert weights to fp16
    zero_kernel<<<(ND + 255) / 256, 256>>>(hstate, h16, ND);
    conv_wg<<<(DDIM * F_IN + 255) / 256, 256>>>(Wg, Wg16);
    conv_w_nk<<<(D3 * DDIM + 255) / 256, 256>>>(Wih, Wih16, D3 * DDIM);
    conv_w_nk<<<(D3 * DDIM + 255) / 256, 256>>>(Whh, Whh16, D3 * DDIM);

    for (int t = 0; t < T_STEPS; t++) {
        // 1) h = x_t @ W_gat (+ fused attention logits + self-loop init)
        gemm_att<<<GX, 256, ATT_SMEM_BYTES>>>(
            x + (long)t * F_IN, T_STEPS * F_IN, N_NODES, Wg16, hf16,
            as, ad, alS, alD, denom, acc);

        // 2) edge pass (fp16 gather, fp32 RED accumulate)
        const int* src = ei + (long)t * 2 * E_EDGES;
        const int* dst = src + E_EDGES;
        edge_kernel<<<(E_EDGES * 32 + 255) / 256, 256>>>(src, dst, alS, alD, hf16, denom, acc);

        // 3) g16 = fp16(relu(acc/denom + b_gat))
        finalize_gat<<<(N_NODES * 32 + 255) / 256, 256>>>(acc, denom, bg, g16);

        // 4) gi = g16 @ Wih^T + b_ih ; gh = h16 @ Whh^T + b_hh (single launch)
        gemm_f16_dual<<<dim3(GX, 6), 256, GEMM_SMEM_BYTES>>>(
            g16, h16, N_NODES, Wih16, Whh16, bih, bhh, gi, gh);

        // 5) GRU update (writes exact h + fp16 copy)
        gru_gates<<<(N_NODES * 32 + 255) / 256, 256>>>(gi, gh, hstate, h16);
    }

    final_linear<<<(N_NODES * 32 + 255) / 256, 256>>>(hstate, Wl, bl, out);
}